// round 6
// baseline (speedup 1.0000x reference)
#include <cuda_runtime.h>

// Problem shapes (fixed by the dataset)
#define BB 16
#define TT 256
#define NPTS 2048
#define TC 4                 // chunks over T
#define FR (TT / TC)         // 64 frames per chunk
#define NSLOTS (BB * TC)     // 64
#define NSTAT 13             // cnt, 3x sum(p), 3x sum(p^2), 3x sum(g), 3x sum(g^2)

// Accumulators (device globals only; no runtime allocation)
__device__ float  g_reduced[NSTAT * NPTS];          // atomic-accumulated per-point stats
__device__ double g_recon, g_temp, g_nvel;

// ---------------------------------------------------------------------------
// K0: zero the accumulators (grid-strided over g_reduced)
// ---------------------------------------------------------------------------
__global__ __launch_bounds__(256)
void k_zero() {
    unsigned tid = blockIdx.x * 256u + threadIdx.x;
    if (tid < NSTAT * NPTS) g_reduced[tid] = 0.f;
    if (tid == 0) { g_recon = 0.0; g_temp = 0.0; g_nvel = 0.0; }
}

// ---------------------------------------------------------------------------
// K1: single streaming pass.
// thread <-> (slot = b*TC + tc, n). Consecutive threads = consecutive n
// => fully coalesced loads. Each thread walks FR frames keeping the previous
// frame in registers for the velocity term, then atomically merges its
// 13 per-point partials straight into g_reduced (no scratch round-trip).
// ---------------------------------------------------------------------------
__global__ __launch_bounds__(256)
void k_main(const float* __restrict__ pred, const float* __restrict__ gt,
            const float* __restrict__ vis) {
    unsigned tid  = blockIdx.x * 256u + threadIdx.x;
    unsigned n    = tid % NPTS;
    unsigned slot = tid / NPTS;          // 0..NSLOTS-1
    unsigned b    = slot / TC;
    unsigned tc   = slot % TC;
    unsigned t0   = tc * FR;

    float cnt = 0.f;
    float spx0=0.f,spx1=0.f,spx2=0.f, spq0=0.f,spq1=0.f,spq2=0.f;
    float sgx0=0.f,sgx1=0.f,sgx2=0.f, sgq0=0.f,sgq1=0.f,sgq2=0.f;
    float recon = 0.f, temporal = 0.f, nvel = 0.f;
    float pp0=0.f,pp1=0.f,pp2=0.f, pg0=0.f,pg1=0.f,pg2=0.f, pm=0.f;

    unsigned rowbase = (b * TT + t0) * NPTS + n;

    if (t0 > 0) {  // preload frame t0-1 for the velocity term
        unsigned pr = rowbase - NPTS;
        unsigned pe = pr * 3u;
        pp0 = pred[pe]; pp1 = pred[pe + 1]; pp2 = pred[pe + 2];
        pg0 = gt[pe];   pg1 = gt[pe + 1];   pg2 = gt[pe + 2];
        pm  = (vis[pr] > 0.5f) ? 1.f : 0.f;
    }

    #pragma unroll 4
    for (unsigned i = 0; i < FR; i++) {
        unsigned t    = t0 + i;
        unsigned ridx = rowbase + i * NPTS;
        unsigned e    = ridx * 3u;
        float p0 = pred[e], p1 = pred[e + 1], p2 = pred[e + 2];
        float g0 = gt[e],   g1 = gt[e + 1],   g2 = gt[e + 2];
        float m  = (vis[ridx] > 0.5f) ? 1.f : 0.f;

        cnt += m;
        float d0 = p0 - g0, d1 = p1 - g1, d2 = p2 - g2;
        recon += m * (d0 * d0 + d1 * d1 + 2.f * d2 * d2);

        spx0 += m * p0; spq0 += m * p0 * p0;
        spx1 += m * p1; spq1 += m * p1 * p1;
        spx2 += m * p2; spq2 += m * p2 * p2;
        sgx0 += m * g0; sgq0 += m * g0 * g0;
        sgx1 += m * g1; sgq1 += m * g1 * g1;
        sgx2 += m * g2; sgq2 += m * g2 * g2;

        if (t > 0) {
            float vm = m * pm;
            float e0 = (p0 - pp0) - (g0 - pg0);
            float e1 = (p1 - pp1) - (g1 - pg1);
            float e2 = (p2 - pp2) - (g2 - pg2);
            temporal += vm * (e0 * e0 + e1 * e1 + e2 * e2);
            nvel     += vm;
        }
        pp0 = p0; pp1 = p1; pp2 = p2;
        pg0 = g0; pg1 = g1; pg2 = g2;
        pm  = m;
    }

    // per-point partials -> direct atomic merge (coalesced over n; 64 writers
    // per address spread over the kernel's lifetime — absorbed by L2 atomics)
    float* r = g_reduced + n;
    atomicAdd(r,              cnt);
    atomicAdd(r + 1  * NPTS,  spx0);  atomicAdd(r + 2  * NPTS, spx1);
    atomicAdd(r + 3  * NPTS,  spx2);  atomicAdd(r + 4  * NPTS, spq0);
    atomicAdd(r + 5  * NPTS,  spq1);  atomicAdd(r + 6  * NPTS, spq2);
    atomicAdd(r + 7  * NPTS,  sgx0);  atomicAdd(r + 8  * NPTS, sgx1);
    atomicAdd(r + 9  * NPTS,  sgx2);  atomicAdd(r + 10 * NPTS, sgq0);
    atomicAdd(r + 11 * NPTS,  sgq1);  atomicAdd(r + 12 * NPTS, sgq2);

    // block-reduce recon / temporal / nvel, one double atomic each per block
    __shared__ float sm[3][8];
    float wr = recon, wt = temporal, wv = nvel;
    #pragma unroll
    for (int o = 16; o > 0; o >>= 1) {
        wr += __shfl_down_sync(0xffffffffu, wr, o);
        wt += __shfl_down_sync(0xffffffffu, wt, o);
        wv += __shfl_down_sync(0xffffffffu, wv, o);
    }
    int lane = threadIdx.x & 31, wid = threadIdx.x >> 5;
    if (lane == 0) { sm[0][wid] = wr; sm[1][wid] = wt; sm[2][wid] = wv; }
    __syncthreads();
    if (wid < 3 && lane < 8) {
        float v = sm[wid][lane];
        #pragma unroll
        for (int o = 4; o > 0; o >>= 1) v += __shfl_down_sync(0xffu, v, o);
        if (lane == 0) {
            if      (wid == 0) atomicAdd(&g_recon, (double)v);
            else if (wid == 1) atomicAdd(&g_temp,  (double)v);
            else               atomicAdd(&g_nvel,  (double)v);
        }
    }
}

// ---------------------------------------------------------------------------
// K2 (fused identity + final): ONE block, 1024 threads, 2 points/thread.
// Full in-block reduction of identity contribution and visible count, then
// thread 0 applies the adaptive re-weighting and writes the 4 outputs.
// ---------------------------------------------------------------------------
__device__ __forceinline__ void point_stats(unsigned n, float& contrib, float& cnt) {
    float c = g_reduced[n];
    float dm = fmaxf(c, 1.f);
    float dv = fmaxf(c - 1.f, 1.f);
    float num = 0.f, den = 0.f;
    #pragma unroll
    for (int k = 0; k < 3; k++) {
        float sx = g_reduced[(1 + k) * NPTS + n];
        float sq = g_reduced[(4 + k) * NPTS + n];
        float mean = sx / dm;
        float pv = (sq - 2.f * mean * sx + c * mean * mean) / dv;
        float gx = g_reduced[(7 + k)  * NPTS + n];
        float gq = g_reduced[(10 + k) * NPTS + n];
        float gmean = gx / dm;
        float gv = (gq - 2.f * gmean * gx + c * gmean * gmean) / dv;
        num += fabsf(pv - gv);
        den += gv;
    }
    float vr = num / (den + 1e-6f);
    contrib += (c > 1.f) ? vr : 0.f;
    cnt     += c;
}

__global__ __launch_bounds__(1024)
void k_ident_final(float* __restrict__ out) {
    unsigned tid = threadIdx.x;
    float contrib = 0.f, cnt = 0.f;
    point_stats(tid,        contrib, cnt);
    point_stats(tid + 1024, contrib, cnt);

    __shared__ float smi[32], smc[32];
    #pragma unroll
    for (int o = 16; o > 0; o >>= 1) {
        contrib += __shfl_down_sync(0xffffffffu, contrib, o);
        cnt     += __shfl_down_sync(0xffffffffu, cnt, o);
    }
    int lane = tid & 31, wid = tid >> 5;
    if (lane == 0) { smi[wid] = contrib; smc[wid] = cnt; }
    __syncthreads();
    if (wid == 0) {
        float vi = smi[lane], vc = smc[lane];
        #pragma unroll
        for (int o = 16; o > 0; o >>= 1) {
            vi += __shfl_down_sync(0xffffffffu, vi, o);
            vc += __shfl_down_sync(0xffffffffu, vc, o);
        }
        if (lane == 0) {
            double nvis = (double)vc;
            double nvel = g_nvel;
            float recon    = (nvis > 0.0) ? (float)(g_recon / fmax(nvis, 1.0)) : 0.f;
            float temporal = (nvel > 0.0) ? (float)(g_temp  / fmax(nvel, 1.0)) : 0.f;
            float identity = vi / (float)NPTS;

            float rl = recon, tl = temporal, il = identity;
            bool  all_pos = (rl > 0.f) && (tl > 0.f) && (il > 0.f);
            float mx     = fmaxf(fmaxf(rl, tl), il);
            float target = mx / 3.f;
            float thresh = 10.f * target;

            float rw = (all_pos && rl > thresh) ? 1.0f * target / fmaxf(rl, 1e-30f) : 1.0f;
            float tw = (all_pos && tl > thresh) ? 0.5f * target / fmaxf(tl, 1e-30f) : 0.5f;
            float iw = (all_pos && il > thresh) ? 0.1f * target / fmaxf(il, 1e-30f) : 0.1f;

            out[0] = rw * recon + tw * temporal + iw * identity;
            out[1] = recon;
            out[2] = temporal;
            out[3] = identity;
        }
    }
}

extern "C" void kernel_launch(void* const* d_in, const int* in_sizes, int n_in,
                              void* d_out, int out_size) {
    const float* pred = (const float*)d_in[0];
    const float* gt   = (const float*)d_in[1];
    const float* vis  = (const float*)d_in[2];
    float* out = (float*)d_out;

    k_zero<<<(NSTAT * NPTS + 255) / 256, 256>>>();
    k_main<<<(NSLOTS * NPTS) / 256, 256>>>(pred, gt, vis);
    k_ident_final<<<1, 1024>>>(out);
}

// round 7
// speedup vs baseline: 1.0384x; 1.0384x over previous
#include <cuda_runtime.h>

// Problem shapes (fixed)
#define BB 16
#define TT 256
#define NPTS 2048
#define NF (NPTS * 3)          // 6144 floats per frame-row
#define NC4 (NF / 4)           // 1536 float4-chunks per frame-row
#define TC 4                   // chunks over T
#define FR (TT / TC)           // 64 frames per thread
#define NSLOTS (BB * TC)       // 64
#define NTHREADS (NSLOTS * NC4)  // 98304
#define BLK 128
#define NBLK (NTHREADS / BLK)  // 768
#define NSTAT 5                // cnt, sum_p, sumsq_p, sum_g, sumsq_g (per channel)

typedef unsigned long long ull;

// Scratch (device globals; no runtime allocation)
__device__ float g_scratch[NSLOTS * NSTAT * NF];   // 7.86 MB, per-channel partials
__device__ float g_bsum[NBLK * 3];                 // per-block recon/temporal/nvel
__device__ float g_red[NSTAT * NF];                // slot-reduced per-channel stats

// ---- packed f32x2 helpers (sm_103a) --------------------------------------
__device__ __forceinline__ ull f2_mul(ull a, ull b) {
    ull d; asm("mul.rn.f32x2 %0,%1,%2;" : "=l"(d) : "l"(a), "l"(b)); return d;
}
__device__ __forceinline__ ull f2_add(ull a, ull b) {
    ull d; asm("add.rn.f32x2 %0,%1,%2;" : "=l"(d) : "l"(a), "l"(b)); return d;
}
__device__ __forceinline__ ull f2_fma(ull a, ull b, ull c) {
    ull d; asm("fma.rn.f32x2 %0,%1,%2,%3;" : "=l"(d) : "l"(a), "l"(b), "l"(c)); return d;
}
__device__ __forceinline__ ull f2_pack(float a, float b) {
    ull r; asm("mov.b64 %0,{%1,%2};" : "=l"(r) : "f"(a), "f"(b)); return r;
}
__device__ __forceinline__ float f2_sum(ull v) {
    float x, y; asm("mov.b64 {%0,%1},%2;" : "=f"(x), "=f"(y) : "l"(v)); return x + y;
}
#define F2_NEG(v) ((v) ^ 0x8000000080000000ULL)
#define D2U(x) __double_as_longlong(x)
#define U2D(x) __longlong_as_double(x)

// ---------------------------------------------------------------------------
// K1: streaming pass, channel-planar mapping.
// thread <-> (slot, c4): owns the 4 consecutive floats [4*c4, 4*c4+4) of every
// frame-row in its T-chunk. All pred/gt loads are lane-contiguous LDG.128
// (4 wavefronts each). Point identity of the 4 floats is fixed per thread
// (phase = c4 % 3); masks come from 2 vis loads (points pA, pA+1).
// ---------------------------------------------------------------------------
__global__ __launch_bounds__(BLK)
void k_main(const float* __restrict__ pred, const float* __restrict__ gt,
            const float* __restrict__ vis) {
    const unsigned tid  = blockIdx.x * BLK + threadIdx.x;
    const unsigned c4   = tid % NC4;           // chunk within frame-row
    const unsigned slot = tid / NC4;           // 0..NSLOTS-1 (uniform per block)
    const unsigned b    = slot / TC;
    const unsigned t0   = (slot % TC) * FR;

    const unsigned phi = c4 % 3;               // 4*c4 mod 3 == c4 mod 3
    const unsigned pA  = (4 * c4) / 3;         // first point touched
    const unsigned pB  = pA + 1;               // second point touched (always valid)
    const bool s1 = (phi == 2);                // pos1 belongs to point B?
    const bool s2 = (phi >= 1);                // pos2 belongs to point B?

    // coord weights per position: coord(pos) = (phi+pos)%3 ; z gets weight 2
    const float w0 = ((phi + 0) % 3 == 2) ? 2.f : 1.f;
    const float w1 = ((phi + 1) % 3 == 2) ? 2.f : 1.f;
    const float w2 = ((phi + 2) % 3 == 2) ? 2.f : 1.f;
    const float w3 = ((phi + 3) % 3 == 2) ? 2.f : 1.f;
    const ull cw_lo = f2_pack(w0, w1);
    const ull cw_hi = f2_pack(w2, w3);

    const double2* __restrict__ pred2 = (const double2*)pred;
    const double2* __restrict__ gt2   = (const double2*)gt;

    // accumulators (f32x2 per channel-pair)
    ull spx0 = 0, spx1 = 0, spq0 = 0, spq1 = 0;
    ull sgx0 = 0, sgx1 = 0, sgq0 = 0, sgq1 = 0;
    ull cnt0 = 0, cnt1 = 0;
    ull recon2 = 0, temp2 = 0, nvel2 = 0;

    // previous-frame state: negated diff and mask
    ull ndplo = 0, ndphi = 0, pmlo = 0, pmhi = 0;

    if (t0 > 0) {  // preload frame t0-1
        unsigned o4 = (b * TT + t0 - 1) * NC4 + c4;
        unsigned ov = (b * TT + t0 - 1) * NPTS;
        double2 p = pred2[o4], g = gt2[o4];
        float vA = vis[ov + pA], vB = vis[ov + pB];
        float mA = (vA > 0.5f) ? 1.f : 0.f;
        float mB = (vB > 0.5f) ? 1.f : 0.f;
        pmlo = f2_pack(mA, s1 ? mB : mA);
        pmhi = f2_pack(s2 ? mB : mA, mB);
        // ndp = g - p  (== -(p-g))
        ndplo = f2_add(D2U(g.x), F2_NEG(D2U(p.x)));
        ndphi = f2_add(D2U(g.y), F2_NEG(D2U(p.y)));
    }

    unsigned o4 = (b * TT + t0) * NC4 + c4;
    unsigned ov = (b * TT + t0) * NPTS;

    #pragma unroll 4
    for (unsigned i = 0; i < FR; i++) {
        double2 p = pred2[o4], g = gt2[o4];
        float vA = vis[ov + pA], vB = vis[ov + pB];
        o4 += NC4; ov += NPTS;

        float mA = (vA > 0.5f) ? 1.f : 0.f;
        float mB = (vB > 0.5f) ? 1.f : 0.f;
        ull mmlo = f2_pack(mA, s1 ? mB : mA);
        ull mmhi = f2_pack(s2 ? mB : mA, mB);

        ull plo = D2U(p.x), phi_ = D2U(p.y);
        ull glo = D2U(g.x), ghi_ = D2U(g.y);

        // per-channel moment sums
        ull mp = f2_mul(mmlo, plo);
        spx0 = f2_add(spx0, mp);  spq0 = f2_fma(mp, plo, spq0);
        mp = f2_mul(mmhi, phi_);
        spx1 = f2_add(spx1, mp);  spq1 = f2_fma(mp, phi_, spq1);
        mp = f2_mul(mmlo, glo);
        sgx0 = f2_add(sgx0, mp);  sgq0 = f2_fma(mp, glo, sgq0);
        mp = f2_mul(mmhi, ghi_);
        sgx1 = f2_add(sgx1, mp);  sgq1 = f2_fma(mp, ghi_, sgq1);
        cnt0 = f2_add(cnt0, mmlo);
        cnt1 = f2_add(cnt1, mmhi);

        // recon: sum w * m * (p-g)^2
        ull dlo = f2_add(plo, F2_NEG(glo));
        ull dhi = f2_add(phi_, F2_NEG(ghi_));
        ull dmlo = f2_mul(dlo, mmlo);
        ull dmhi = f2_mul(dhi, mmhi);
        recon2 = f2_fma(f2_mul(dmlo, cw_lo), dmlo, recon2);
        recon2 = f2_fma(f2_mul(dmhi, cw_hi), dmhi, recon2);

        // temporal: e = d - d_prev, masked by m*m_prev
        ull elo = f2_add(dlo, ndplo);
        ull ehi = f2_add(dhi, ndphi);
        ull vmlo = f2_mul(mmlo, pmlo);
        ull vmhi = f2_mul(mmhi, pmhi);
        temp2 = f2_fma(f2_mul(elo, vmlo), elo, temp2);
        temp2 = f2_fma(f2_mul(ehi, vmhi), ehi, temp2);
        nvel2 = f2_add(nvel2, vmlo);
        nvel2 = f2_add(nvel2, vmhi);    // counts each point 3x -> /3 later

        ndplo = F2_NEG(dlo); ndphi = F2_NEG(dhi);
        pmlo = mmlo; pmhi = mmhi;
    }

    // per-channel partials -> scratch (coalesced STG.128 per stat)
    {
        double2* s = (double2*)g_scratch;
        unsigned base = slot * (NSTAT * NC4) + c4;   // double2 index
        double2 v;
        v.x = U2D(cnt0); v.y = U2D(cnt1); s[base]           = v;
        v.x = U2D(spx0); v.y = U2D(spx1); s[base + 1 * NC4] = v;
        v.x = U2D(spq0); v.y = U2D(spq1); s[base + 2 * NC4] = v;
        v.x = U2D(sgx0); v.y = U2D(sgx1); s[base + 3 * NC4] = v;
        v.x = U2D(sgq0); v.y = U2D(sgq1); s[base + 4 * NC4] = v;
    }

    // block-reduce recon/temporal/nvel -> per-block partial (no atomics)
    float wr = f2_sum(recon2), wt = f2_sum(temp2), wv = f2_sum(nvel2);
    __shared__ float sm[4][3];
    #pragma unroll
    for (int o = 16; o > 0; o >>= 1) {
        wr += __shfl_down_sync(0xffffffffu, wr, o);
        wt += __shfl_down_sync(0xffffffffu, wt, o);
        wv += __shfl_down_sync(0xffffffffu, wv, o);
    }
    int lane = threadIdx.x & 31, wid = threadIdx.x >> 5;
    if (lane == 0) { sm[wid][0] = wr; sm[wid][1] = wt; sm[wid][2] = wv; }
    __syncthreads();
    if (threadIdx.x < 3) {
        int k = threadIdx.x;
        g_bsum[blockIdx.x * 3 + k] = sm[0][k] + sm[1][k] + sm[2][k] + sm[3][k];
    }
}

// ---------------------------------------------------------------------------
// K2: fold the 64 slots per (stat, channel). Coalesced; 7.9 MB read.
// ---------------------------------------------------------------------------
__global__ __launch_bounds__(256)
void k_reduce() {
    unsigned tid = blockIdx.x * 256u + threadIdx.x;   // stat*NF + ch
    if (tid >= NSTAT * NF) return;
    float s = 0.f;
    #pragma unroll 8
    for (int slot = 0; slot < NSLOTS; slot++)
        s += g_scratch[(unsigned)slot * (NSTAT * NF) + tid];
    g_red[tid] = s;
}

// ---------------------------------------------------------------------------
// K3: identity (per-point variance ratio over L2-hot g_red) + block-partial
// fold + adaptive re-weighting. One block, 512 threads.
// ---------------------------------------------------------------------------
__global__ __launch_bounds__(512)
void k_final(float* __restrict__ out) {
    int tid = threadIdx.x;

    float ident = 0.f, cntsum = 0.f;
    #pragma unroll
    for (int n = tid; n < NPTS; n += 512) {
        float c  = g_red[3 * n];                      // cnt (channel 3n, coord x)
        float dm = fmaxf(c, 1.f);
        float dv = fmaxf(c - 1.f, 1.f);
        float num = 0.f, den = 0.f;
        #pragma unroll
        for (int k = 0; k < 3; k++) {
            int ch = 3 * n + k;
            float sx = g_red[1 * NF + ch];
            float sq = g_red[2 * NF + ch];
            float mean = sx / dm;
            float pv = (sq - 2.f * mean * sx + c * mean * mean) / dv;
            float gx = g_red[3 * NF + ch];
            float gq = g_red[4 * NF + ch];
            float gmean = gx / dm;
            float gv = (gq - 2.f * gmean * gx + c * gmean * gmean) / dv;
            num += fabsf(pv - gv);
            den += gv;
        }
        float vr = num / (den + 1e-6f);
        ident  += (c > 1.f) ? vr : 0.f;
        cntsum += c;
    }

    double racc = 0.0, tacc = 0.0, vacc = 0.0;
    for (int j = tid; j < NBLK; j += 512) {
        racc += (double)g_bsum[j * 3 + 0];
        tacc += (double)g_bsum[j * 3 + 1];
        vacc += (double)g_bsum[j * 3 + 2];
    }

    // block reduction of 5 quantities
    __shared__ double sr[5][16];
    double di = ident, dc = cntsum;
    #pragma unroll
    for (int o = 16; o > 0; o >>= 1) {
        di   += __shfl_down_sync(0xffffffffu, di, o);
        dc   += __shfl_down_sync(0xffffffffu, dc, o);
        racc += __shfl_down_sync(0xffffffffu, racc, o);
        tacc += __shfl_down_sync(0xffffffffu, tacc, o);
        vacc += __shfl_down_sync(0xffffffffu, vacc, o);
    }
    int lane = tid & 31, wid = tid >> 5;
    if (lane == 0) {
        sr[0][wid] = di; sr[1][wid] = dc; sr[2][wid] = racc;
        sr[3][wid] = tacc; sr[4][wid] = vacc;
    }
    __syncthreads();
    if (wid == 0 && lane < 16) {
        di = sr[0][lane]; dc = sr[1][lane]; racc = sr[2][lane];
        tacc = sr[3][lane]; vacc = sr[4][lane];
        #pragma unroll
        for (int o = 8; o > 0; o >>= 1) {
            di   += __shfl_down_sync(0xffffu, di, o);
            dc   += __shfl_down_sync(0xffffu, dc, o);
            racc += __shfl_down_sync(0xffffu, racc, o);
            tacc += __shfl_down_sync(0xffffu, tacc, o);
            vacc += __shfl_down_sync(0xffffu, vacc, o);
        }
        if (lane == 0) {
            double nvis = dc;
            double nvel = vacc / 3.0;    // channels triple-count each point
            float recon    = (nvis > 0.0) ? (float)(racc / fmax(nvis, 1.0)) : 0.f;
            float temporal = (nvel > 0.0) ? (float)(tacc / fmax(nvel, 1.0)) : 0.f;
            float identity = (float)(di / (double)NPTS);

            float rl = recon, tl = temporal, il = identity;
            bool  all_pos = (rl > 0.f) && (tl > 0.f) && (il > 0.f);
            float mx     = fmaxf(fmaxf(rl, tl), il);
            float target = mx / 3.f;
            float thresh = 10.f * target;

            float rw = (all_pos && rl > thresh) ? 1.0f * target / fmaxf(rl, 1e-30f) : 1.0f;
            float tw = (all_pos && tl > thresh) ? 0.5f * target / fmaxf(tl, 1e-30f) : 0.5f;
            float iw = (all_pos && il > thresh) ? 0.1f * target / fmaxf(il, 1e-30f) : 0.1f;

            out[0] = rw * recon + tw * temporal + iw * identity;
            out[1] = recon;
            out[2] = temporal;
            out[3] = identity;
        }
    }
}

extern "C" void kernel_launch(void* const* d_in, const int* in_sizes, int n_in,
                              void* d_out, int out_size) {
    const float* pred = (const float*)d_in[0];
    const float* gt   = (const float*)d_in[1];
    const float* vis  = (const float*)d_in[2];
    float* out = (float*)d_out;

    k_main<<<NBLK, BLK>>>(pred, gt, vis);
    k_reduce<<<(NSTAT * NF + 255) / 256, 256>>>();
    k_final<<<1, 512>>>(out);
}